// round 10
// baseline (speedup 1.0000x reference)
#include <cuda_runtime.h>
#include <cuda_fp16.h>
#include <cstdint>

#define BRN 32768
#define DN 512
#define HN 1024
#define NRELN 2048
#define ROWS2 65536

__device__ float g_attn[(size_t)BRN * DN];
__device__ float g_Wc[DN * DN];
__device__ float g_bc[DN];
__device__ uint8_t g_ximg[(size_t)(BRN/128)*(DN/16)*8192];
__device__ uint8_t g_wcimg[(size_t)(DN/128)*(DN/16)*8192];
__device__ uint8_t g_himg[(size_t)(ROWS2/128)*(DN/16)*8192];
__device__ uint8_t g_w1img[(size_t)(HN/128)*(DN/16)*8192];
__device__ uint8_t g_gh[(size_t)(ROWS2/128)*(HN/16)*4096];   // hi-only dense A image
__device__ float   g_f32[(size_t)ROWS2 * HN];                // exact fp32 g
__device__ uint8_t g_w2h[(size_t)(NRELN/128)*(HN/16)*4096];  // hi-only dense B image
__device__ float g_sum[ROWS2];
__device__ float g_cv4[ROWS2 * 4];
__device__ int   g_ci4[ROWS2 * 4];
__device__ float g_lmax[ROWS2];
__device__ int   g_arg[ROWS2];

__device__ __forceinline__ uint32_t smem_u32(const void* p){
    uint32_t a; asm("{ .reg .u64 t; cvta.to.shared.u64 t, %1; cvt.u32.u64 %0, t; }" : "=r"(a) : "l"(p)); return a;
}
__device__ __forceinline__ void cpa16(uint32_t d, const void* s){
    asm volatile("cp.async.cg.shared.global [%0],[%1],16;" :: "r"(d), "l"(s));
}
__device__ __forceinline__ void hmma(float* c, const uint32_t* a, uint32_t b0, uint32_t b1){
    asm volatile("mma.sync.aligned.m16n8k16.row.col.f32.f16.f16.f32 {%0,%1,%2,%3},{%4,%5,%6,%7},{%8,%9},{%0,%1,%2,%3};"
        : "+f"(c[0]), "+f"(c[1]), "+f"(c[2]), "+f"(c[3])
        : "r"(a[0]), "r"(a[1]), "r"(a[2]), "r"(a[3]), "r"(b0), "r"(b1));
}
__device__ __forceinline__ float fexp(float x){
    return __uint_as_float((uint32_t)(int)(fmaf(x, 12102203.0f, 1064866805.0f)));
}
__device__ __forceinline__ uint32_t hpack(float x, float y){
    return (uint32_t)__half_as_ushort(__float2half_rn(x)) | ((uint32_t)__half_as_ushort(__float2half_rn(y)) << 16);
}
__device__ __forceinline__ void hsplit2(float x, float y, uint32_t& hi, uint32_t& lo){
    __half hx = __float2half_rn(x), hy = __float2half_rn(y);
    __half lx = __float2half_rn(x - __half2float(hx)), ly = __float2half_rn(y - __half2float(hy));
    hi = (uint32_t)__half_as_ushort(hx) | ((uint32_t)__half_as_ushort(hy) << 16);
    lo = (uint32_t)__half_as_ushort(lx) | ((uint32_t)__half_as_ushort(ly) << 16);
}
__device__ __forceinline__ size_t aoff(int row, int k, int plane, int KT){
    int mblk = row >> 7, mi = (row >> 4) & 7, g = row & 7, rb = (row >> 3) & 1;
    int kt = k >> 4, tg = (k >> 1) & 3, kb = (k >> 3) & 1;
    return (size_t)(mblk * KT + kt) * 8192 + (size_t)((((plane*8 + mi)*32 + g*4 + tg)*4 + rb + 2*kb) * 4);
}
__device__ __forceinline__ size_t boff(int n, int k, int plane, int KT){
    int nblk = n >> 7, nj = (n >> 3) & 15, g = n & 7;
    int kt = k >> 4, tg = (k >> 1) & 3, kb = (k >> 3) & 1;
    return (size_t)(nblk * KT + kt) * 8192 + (size_t)(((((nj*32 + g*4 + tg)*2 + plane)*2 + kb)) * 4);
}
// descending insert into sorted-4, strict > (earlier wins ties)
__device__ __forceinline__ void ins4(float* v, int* x, float nv, int ni){
    if (nv <= v[3]) return;
    v[3] = nv; x[3] = ni;
    if (v[3] > v[2]){ float tv=v[2]; v[2]=v[3]; v[3]=tv; int ti=x[2]; x[2]=x[3]; x[3]=ti;
      if (v[2] > v[1]){ tv=v[1]; v[1]=v[2]; v[2]=tv; ti=x[1]; x[1]=x[2]; x[2]=ti;
        if (v[1] > v[0]){ tv=v[0]; v[0]=v[1]; v[1]=tv; ti=x[0]; x[0]=x[1]; x[1]=ti; } } }
}

// ============ combine W ============
__global__ void combine_w_kernel(const float* __restrict__ o_w, const float* __restrict__ v_w,
                                 const float* __restrict__ v_b, const float* __restrict__ o_b){
    int i = blockIdx.x, tx = threadIdx.x;
    __shared__ float orow[DN];
    for (int k = tx; k < DN; k += 256) orow[k] = o_w[i*DN + k];
    __syncthreads();
    float a0 = 0.f, a1 = 0.f;
    for (int k = 0; k < DN; k++){ float a = orow[k];
        a0 = fmaf(a, v_w[k*DN + tx], a0); a1 = fmaf(a, v_w[k*DN + tx + 256], a1); }
    g_Wc[i*DN + tx] = a0; g_Wc[i*DN + tx + 256] = a1;
    if (tx == 0){ float b = o_b[i];
        for (int k = 0; k < DN; k++) b = fmaf(orow[k], v_b[k], b);
        g_bc[i] = b; }
}

// ============ weight -> both-plane B image (wc, w1) ============
__global__ void wsplit_kernel(const float* __restrict__ w, uint8_t* __restrict__ img, int K, int ksh){
    int id = blockIdx.x*256 + threadIdx.x;
    int kp = id & ((K >> 1) - 1), n = id >> ksh, k = kp*2;
    uint32_t hi, lo; hsplit2(w[(size_t)n*K + k], w[(size_t)n*K + k + 1], hi, lo);
    int KT = K >> 4;
    *(uint32_t*)(img + boff(n, k, 0, KT)) = hi;
    *(uint32_t*)(img + boff(n, k, 1, KT)) = lo;
}
// ============ w2 -> hi-only dense B image ============
__global__ void wsplit_hi_kernel(const float* __restrict__ w){
    int id = blockIdx.x*256 + threadIdx.x;
    int kp = id & (HN/2 - 1), n = id >> 9, k = kp*2;
    uint32_t hi = hpack(w[(size_t)n*HN + k], w[(size_t)n*HN + k + 1]);
    int nblk = n >> 7, nj = (n >> 3) & 15, g = n & 7;
    int kt = k >> 4, tg = (k >> 1) & 3, kb = (k >> 3) & 1;
    *(uint32_t*)(g_w2h + (size_t)(nblk*64 + kt)*4096 + ((nj*32 + g*4 + tg)*2 + kb)*4) = hi;
}

// ============ x -> A fragment image ============
__global__ void xsplit_kernel(const float* __restrict__ x){
    int id = blockIdx.x*256 + threadIdx.x;
    int tg = id & 3, g = (id >> 2) & 7, mi = (id >> 5) & 7, kt = (id >> 8) & 31, mblk = id >> 13;
    uint32_t p0[4], p1[4];
#pragma unroll
    for (int rb = 0; rb < 2; rb++)
#pragma unroll
        for (int kb = 0; kb < 2; kb++){
            int row = mblk*128 + mi*16 + rb*8 + g;
            int k = kt*16 + kb*8 + tg*2;
            float2 v = *(const float2*)&x[(size_t)row*DN + k];
            hsplit2(v.x, v.y, p0[rb + 2*kb], p1[rb + 2*kb]);
        }
    size_t base = (size_t)(mblk*32 + kt)*8192 + (size_t)((mi*32 + g*4 + tg)*16);
    *(uint4*)(g_ximg + base)        = *(uint4*)p0;
    *(uint4*)(g_ximg + base + 4096) = *(uint4*)p1;
}

// ============ 3-product HMMA mainloop (attn, gemm_g) ============
__device__ __forceinline__ void issue_cp(char* smbuf, const uint8_t* A, const uint8_t* B, int tid){
    uint32_t d = smem_u32(smbuf) + (uint32_t)tid*32u;
    cpa16(d,      A + tid*32); cpa16(d + 16,        A + tid*32 + 16);
    cpa16(d+8192, B + tid*32); cpa16(d + 8192 + 16, B + tid*32 + 16);
    asm volatile("cp.async.commit_group;" ::: "memory");
}
__device__ __forceinline__ void mloop(const uint8_t* Ab, const uint8_t* Bb, int KT,
                                      char* sm, float acc[4][4][4], int tid, int wm, int wn, int lane){
    issue_cp(sm,         Ab,        Bb,        tid);
    issue_cp(sm + 16384, Ab + 8192, Bb + 8192, tid);
    for (int t = 0; t < KT; t++){
        if (t + 1 < KT) asm volatile("cp.async.wait_group 1;" ::: "memory");
        else            asm volatile("cp.async.wait_group 0;" ::: "memory");
        __syncthreads();
        if (t + 2 < KT)
            issue_cp(sm + ((t+2)%3)*16384, Ab + (size_t)(t+2)*8192, Bb + (size_t)(t+2)*8192, tid);
        char* base = sm + (t%3)*16384;
        uint32_t ah[4][4], al[4][4];
#pragma unroll
        for (int mi = 0; mi < 4; mi++){
            *(uint4*)ah[mi] = *(const uint4*)(base + (((wm*4+mi))*32 + lane)*16);
            *(uint4*)al[mi] = *(const uint4*)(base + ((8 + wm*4+mi)*32 + lane)*16);
        }
#pragma unroll
        for (int nj = 0; nj < 4; nj++){
            uint4 bv = *(const uint4*)(base + 8192 + ((wn*4+nj)*32 + lane)*16);
#pragma unroll
            for (int mi = 0; mi < 4; mi++){
                hmma(acc[mi][nj], ah[mi], bv.x, bv.y);
                hmma(acc[mi][nj], ah[mi], bv.z, bv.w);
                hmma(acc[mi][nj], al[mi], bv.x, bv.y);
            }
        }
    }
    __syncthreads();
}

// ============ attn = x @ WcT + bc ============
__global__ __launch_bounds__(256, 2)
void attn_tc(){
    __shared__ __align__(16) char sm[49152];
    int tid = threadIdx.x, wid = tid >> 5, lane = tid & 31, wm = wid & 1, wn = wid >> 1;
    int gid = lane >> 2, tig = lane & 3;
    int m0 = blockIdx.y*128, n0 = blockIdx.x*128;
    float acc[4][4][4] = {};
    mloop(g_ximg + (size_t)blockIdx.y*(DN/16)*8192, g_wcimg + (size_t)blockIdx.x*(DN/16)*8192,
          DN/16, sm, acc, tid, wm, wn, lane);
#pragma unroll
    for (int mi = 0; mi < 4; mi++)
#pragma unroll
        for (int nj = 0; nj < 4; nj++){
            int col = n0 + wn*32 + nj*8 + tig*2;
            float bx = g_bc[col], by = g_bc[col+1];
#pragma unroll
            for (int h = 0; h < 2; h++){
                int row = m0 + wm*64 + mi*16 + gid + h*8;
                float2 v = {acc[mi][nj][2*h] + bx, acc[mi][nj][2*h+1] + by};
                *(float2*)&g_attn[(size_t)row*DN + col] = v;
            }
        }
}

// ============ LN(attn+state) -> fp16 hi/lo A-image ============
__global__ __launch_bounds__(128)
void ln_split_kernel(const float* __restrict__ x, const float* __restrict__ na,
                     const float* __restrict__ lng, const float* __restrict__ lnb){
    int rr = blockIdx.x, tx = threadIdx.x, r = rr & (BRN-1);
    const float* sp = (rr < BRN) ? (na + tx*4) : (x + (size_t)r*DN + tx*4);
    float4 a = *(const float4*)&g_attn[(size_t)r*DN + tx*4];
    float4 s = *(const float4*)sp;
    float vx = a.x+s.x, vy = a.y+s.y, vz = a.z+s.z, vw = a.w+s.w;
    float sum = vx+vy+vz+vw, sq = vx*vx+vy*vy+vz*vz+vw*vw;
#pragma unroll
    for (int o = 16; o > 0; o >>= 1){
        sum += __shfl_xor_sync(0xffffffff, sum, o); sq += __shfl_xor_sync(0xffffffff, sq, o); }
    __shared__ float sh[8];
    int w = tx >> 5;
    if ((tx & 31) == 0){ sh[w] = sum; sh[4+w] = sq; }
    __syncthreads();
    float ts = sh[0]+sh[1]+sh[2]+sh[3], ts2 = sh[4]+sh[5]+sh[6]+sh[7];
    float mean = ts*(1.f/DN), rstd = rsqrtf(ts2*(1.f/DN) - mean*mean + 1e-5f);
    float4 g = *(const float4*)&lng[tx*4];
    float4 b = *(const float4*)&lnb[tx*4];
    float o0 = fmaf((vx-mean)*rstd, g.x, b.x), o1 = fmaf((vy-mean)*rstd, g.y, b.y);
    float o2 = fmaf((vz-mean)*rstd, g.z, b.z), o3 = fmaf((vw-mean)*rstd, g.w, b.w);
    uint32_t h0, l0, h1, l1; hsplit2(o0, o1, h0, l0); hsplit2(o2, o3, h1, l1);
    int k = tx*4; const int KT = DN/16;
    *(uint32_t*)(g_himg + aoff(rr, k,   0, KT)) = h0;
    *(uint32_t*)(g_himg + aoff(rr, k,   1, KT)) = l0;
    *(uint32_t*)(g_himg + aoff(rr, k+2, 0, KT)) = h1;
    *(uint32_t*)(g_himg + aoff(rr, k+2, 1, KT)) = l1;
}

// ============ g = relu(h @ w1T + b1) -> hi-dense image + fp32 ============
__global__ __launch_bounds__(256, 2)
void gemm_g_tc(const float* __restrict__ b1){
    __shared__ __align__(16) char sm[49152];
    int tid = threadIdx.x, wid = tid >> 5, lane = tid & 31, wm = wid & 1, wn = wid >> 1;
    int gid = lane >> 2, tig = lane & 3;
    int m0 = blockIdx.y*128, n0 = blockIdx.x*128;
    float acc[4][4][4] = {};
    mloop(g_himg + (size_t)blockIdx.y*(DN/16)*8192, g_w1img + (size_t)blockIdx.x*(DN/16)*8192,
          DN/16, sm, acc, tid, wm, wn, lane);
    const int KT = HN/16;
    float bxv[4], byv[4];
#pragma unroll
    for (int nj = 0; nj < 4; nj++){
        int col = n0 + wn*32 + nj*8 + tig*2;
        bxv[nj] = __ldg(&b1[col]); byv[nj] = __ldg(&b1[col+1]);
    }
#pragma unroll
    for (int mi = 0; mi < 4; mi++)
#pragma unroll
        for (int njp = 0; njp < 2; njp++){
            uint32_t q0[4];
#pragma unroll
            for (int q = 0; q < 2; q++){
                int nj = njp*2 + q;
#pragma unroll
                for (int h = 0; h < 2; h++){
                    float v0 = fmaxf(acc[mi][nj][2*h]   + bxv[nj], 0.f);
                    float v1 = fmaxf(acc[mi][nj][2*h+1] + byv[nj], 0.f);
                    q0[h + 2*q] = hpack(v0, v1);
                    int row = m0 + wm*64 + mi*16 + gid + h*8;
                    int col = n0 + wn*32 + nj*8 + tig*2;
                    float2 fv = {v0, v1};
                    *(float2*)&g_f32[(size_t)row*HN + col] = fv;
                }
            }
            int kt = (n0 + wn*32 + njp*16) >> 4;
            size_t base = (size_t)(blockIdx.y*KT + kt)*4096
                        + (size_t)(((wm*4 + mi)*32 + gid*4 + tig)*16);
            *(uint4*)(g_gh + base) = *(uint4*)q0;
        }
}

// ============ logits pass A: hi-only HMMA, top-4 candidates + approx sumexp ============
// dyn smem: stages 3x8192 | cand_val 32768 | cand_idx 32768 | ssum 8192 = 98304
__device__ __forceinline__ void issue_cp_hi(char* smbuf, const uint8_t* A, const uint8_t* B, int tid){
    uint32_t d = smem_u32(smbuf) + (uint32_t)tid*16u;
    cpa16(d, A + tid*16); cpa16(d + 4096, B + tid*16);
    asm volatile("cp.async.commit_group;" ::: "memory");
}
__global__ __launch_bounds__(256, 2)
void logits_hi(const float* __restrict__ b2){
    extern __shared__ char dsm[];
    float* cv = (float*)(dsm + 24576);
    int*   ci = (int*)(dsm + 57344);
    float* ss = (float*)(dsm + 90112);
    int tid = threadIdx.x, wid = tid >> 5, lane = tid & 31, wm = wid & 1, wn = wid >> 1;
    int gid = lane >> 2, tig = lane & 3, m0 = blockIdx.x*128;
    for (int i = tid; i < 128*16*4; i += 256){ cv[i] = -1e30f; ci[i] = 0; }
    float su[8], gate[8];
#pragma unroll
    for (int s = 0; s < 8; s++){ su[s] = 0.f; gate[s] = -1e30f; }
    __syncthreads();
    const uint8_t* Ab = g_gh + (size_t)blockIdx.x*64*4096;
    for (int nt = 0; nt < 16; nt++){
        const uint8_t* Bb = g_w2h + (size_t)nt*64*4096;
        float acc[4][4][4] = {};
        issue_cp_hi(dsm,        Ab,        Bb,        tid);
        issue_cp_hi(dsm + 8192, Ab + 4096, Bb + 4096, tid);
        for (int t = 0; t < 64; t++){
            if (t + 1 < 64) asm volatile("cp.async.wait_group 1;" ::: "memory");
            else            asm volatile("cp.async.wait_group 0;" ::: "memory");
            __syncthreads();
            if (t + 2 < 64)
                issue_cp_hi(dsm + ((t+2)%3)*8192, Ab + (size_t)(t+2)*4096, Bb + (size_t)(t+2)*4096, tid);
            char* base = dsm + (t%3)*8192;
            uint32_t ah[4][4];
#pragma unroll
            for (int mi = 0; mi < 4; mi++)
                *(uint4*)ah[mi] = *(const uint4*)(base + ((wm*4+mi)*32 + lane)*16);
#pragma unroll
            for (int nj = 0; nj < 4; nj++){
                uint2 bv = *(const uint2*)(base + 4096 + ((wn*4+nj)*32 + lane)*8);
#pragma unroll
                for (int mi = 0; mi < 4; mi++)
                    hmma(acc[mi][nj], ah[mi], bv.x, bv.y);
            }
        }
        __syncthreads();
#pragma unroll
        for (int nj = 0; nj < 4; nj++){
            int cb = nt*128 + wn*32 + nj*8 + tig*2;
            float bx = __ldg(&b2[cb]), by = __ldg(&b2[cb+1]);
#pragma unroll
            for (int mi = 0; mi < 4; mi++)
#pragma unroll
                for (int h = 0; h < 2; h++){
                    int s = mi*2 + h;
                    float l0 = acc[mi][nj][2*h] + bx, l1 = acc[mi][nj][2*h+1] + by;
                    su[s] += fexp(l0) + fexp(l1);
                    float m2 = fmaxf(l0, l1);
                    if (m2 > gate[s]){
                        int row = wm*64 + mi*16 + gid + h*8, sc = wn*4 + tig;
                        float* v = cv + (row*16 + sc)*4;
                        int*   x = ci + (row*16 + sc)*4;
                        ins4(v, x, l0, cb);
                        ins4(v, x, l1, cb + 1);
                        gate[s] = v[3];
                    }
                }
        }
    }
#pragma unroll
    for (int mi = 0; mi < 4; mi++)
#pragma unroll
        for (int h = 0; h < 2; h++){
            int row = wm*64 + mi*16 + gid + h*8, sc = wn*4 + tig;
            ss[row*16 + sc] = su[mi*2 + h];
        }
    __syncthreads();
    if (tid < 128){
        int row = tid;
        float t = 0.f;
#pragma unroll
        for (int i = 0; i < 16; i++) t += ss[row*16 + i];
        g_sum[m0 + row] = t;
        float bv[4] = {-1e30f, -1e30f, -1e30f, -1e30f};
        int   bi[4] = {0, 0, 0, 0};
        for (int i = 0; i < 64; i++)
            ins4(bv, bi, cv[row*64 + i], ci[row*64 + i]);
#pragma unroll
        for (int j = 0; j < 4; j++){
            g_cv4[(m0 + row)*4 + j] = bv[j];
            g_ci4[(m0 + row)*4 + j] = bi[j];
        }
    }
}

// ============ rescue: exact fp32 rescore of 4 candidates, warp per row ============
__global__ __launch_bounds__(256)
void rescue_kernel(const float* __restrict__ w2, const float* __restrict__ b2){
    int row = blockIdx.x*8 + (threadIdx.x >> 5);
    int lane = threadIdx.x & 31;
    float bestv = -1e30f; int besti = 0;
    const float* gr = g_f32 + (size_t)row * HN;
#pragma unroll 1
    for (int j = 0; j < 4; j++){
        int c = g_ci4[row*4 + j];
        const float* wr = w2 + (size_t)c * HN;
        float p = 0.f;
        for (int k = lane; k < HN; k += 32) p = fmaf(gr[k], wr[k], p);
#pragma unroll
        for (int o = 16; o > 0; o >>= 1) p += __shfl_xor_sync(0xffffffff, p, o);
        p += __ldg(&b2[c]);
        if (p > bestv || (p == bestv && c < besti)){ bestv = p; besti = c; }
    }
    if (lane == 0){ g_lmax[row] = bestv; g_arg[row] = besti; }
}

// ============ finalize ============
__global__ void finalize_kernel(float* __restrict__ out){
    int r = blockIdx.x*256 + threadIdx.x;
    if (r >= BRN) return;
    float m0 = __expf(g_lmax[r]) / g_sum[r];
    float m1 = __expf(g_lmax[BRN + r]) / g_sum[BRN + r];
    int i0 = g_arg[r], i1 = g_arg[BRN + r];
    bool c0 = (i0 != 0) && (m0 >= 0.1f);
    bool c1 = c0 && (i1 != 0) && (m1 >= 0.1f);
    out[r] = c0 ? (c1 ? m0*m1 : m0) : 0.f;
    out[BRN + r] = (float)i0; out[2*BRN + r] = (float)i1;
    out[3*BRN + r] = (float)((int)c0 + (int)c1);
}

extern "C" void kernel_launch(void* const* d_in, const int* in_sizes, int n_in,
                              void* d_out, int out_size){
    const float* x    = (const float*)d_in[0];
    const float* na   = (const float*)d_in[1];
    const float* v_w  = (const float*)d_in[2];
    const float* v_b  = (const float*)d_in[3];
    const float* o_w  = (const float*)d_in[4];
    const float* o_b  = (const float*)d_in[5];
    const float* ln_g = (const float*)d_in[6];
    const float* ln_b = (const float*)d_in[7];
    const float* w1   = (const float*)d_in[8];
    const float* b1   = (const float*)d_in[9];
    const float* w2   = (const float*)d_in[10];
    const float* b2   = (const float*)d_in[11];
    float* out = (float*)d_out;

    float* wc; cudaGetSymbolAddress((void**)&wc, g_Wc);
    uint8_t *wcimg, *w1img;
    cudaGetSymbolAddress((void**)&wcimg, g_wcimg);
    cudaGetSymbolAddress((void**)&w1img, g_w1img);
    cudaFuncSetAttribute(logits_hi, cudaFuncAttributeMaxDynamicSharedMemorySize, 98304);

    combine_w_kernel<<<DN, 256>>>(o_w, v_w, v_b, o_b);
    wsplit_kernel<<<(DN*DN/2)/256, 256>>>(wc, wcimg, DN, 8);
    wsplit_kernel<<<(HN*DN/2)/256, 256>>>(w1, w1img, DN, 8);
    wsplit_hi_kernel<<<((size_t)NRELN*HN/2)/256, 256>>>(w2);
    xsplit_kernel<<<(BRN*DN/8)/256, 256>>>(x);
    attn_tc<<<dim3(DN/128, BRN/128), 256>>>();
    ln_split_kernel<<<ROWS2, 128>>>(x, na, ln_g, ln_b);
    gemm_g_tc<<<dim3(HN/128, ROWS2/128), 256>>>(b1);
    logits_hi<<<ROWS2/128, 256, 98304>>>(b2);
    rescue_kernel<<<ROWS2/8, 256>>>(w2, b2);
    finalize_kernel<<<BRN/256, 256>>>(out);
}

// round 11
// speedup vs baseline: 1.7962x; 1.7962x over previous
#include <cuda_runtime.h>
#include <cuda_fp16.h>
#include <cstdint>

#define BRN 32768
#define DN 512
#define HN 1024
#define NRELN 2048
#define ROWS2 65536
typedef unsigned long long ull;

__device__ float g_attn[(size_t)BRN * DN];
__device__ float g_Wc[DN * DN];
__device__ float g_bc[DN];
__device__ uint8_t g_ximg[(size_t)(BRN/128)*(DN/16)*8192];
__device__ uint8_t g_wcimg[(size_t)(DN/128)*(DN/16)*8192];
__device__ uint8_t g_himg[(size_t)(ROWS2/128)*(DN/16)*8192];
__device__ uint8_t g_w1img[(size_t)(HN/128)*(DN/16)*8192];
__device__ uint8_t g_gimg[(size_t)(ROWS2/128)*(HN/16)*8192];
__device__ uint8_t g_w2h[(size_t)(NRELN/128)*(HN/16)*4096];
__device__ float   g_f32[(size_t)ROWS2 * HN];
__device__ float g_sum[ROWS2];
__device__ int   g_ci4[ROWS2 * 4];
__device__ float g_lmax[ROWS2];
__device__ int   g_arg[ROWS2];

__device__ __forceinline__ uint32_t smem_u32(const void* p){
    uint32_t a; asm("{ .reg .u64 t; cvta.to.shared.u64 t, %1; cvt.u32.u64 %0, t; }" : "=r"(a) : "l"(p)); return a;
}
__device__ __forceinline__ void cpa16(uint32_t d, const void* s){
    asm volatile("cp.async.cg.shared.global [%0],[%1],16;" :: "r"(d), "l"(s));
}
__device__ __forceinline__ void hmma(float* c, const uint32_t* a, uint32_t b0, uint32_t b1){
    asm volatile("mma.sync.aligned.m16n8k16.row.col.f32.f16.f16.f32 {%0,%1,%2,%3},{%4,%5,%6,%7},{%8,%9},{%0,%1,%2,%3};"
        : "+f"(c[0]), "+f"(c[1]), "+f"(c[2]), "+f"(c[3])
        : "r"(a[0]), "r"(a[1]), "r"(a[2]), "r"(a[3]), "r"(b0), "r"(b1));
}
__device__ __forceinline__ float fexp(float x){
    x = fmaxf(x, -80.f);
    return __uint_as_float((uint32_t)(int)(fmaf(x, 12102203.0f, 1064866805.0f)));
}
__device__ __forceinline__ uint32_t hpack(float x, float y){
    return (uint32_t)__half_as_ushort(__float2half_rn(x)) | ((uint32_t)__half_as_ushort(__float2half_rn(y)) << 16);
}
__device__ __forceinline__ void hsplit2(float x, float y, uint32_t& hi, uint32_t& lo){
    __half hx = __float2half_rn(x), hy = __float2half_rn(y);
    __half lx = __float2half_rn(x - __half2float(hx)), ly = __float2half_rn(y - __half2float(hy));
    hi = (uint32_t)__half_as_ushort(hx) | ((uint32_t)__half_as_ushort(hy) << 16);
    lo = (uint32_t)__half_as_ushort(lx) | ((uint32_t)__half_as_ushort(ly) << 16);
}
__device__ __forceinline__ size_t aoff(int row, int k, int plane, int KT){
    int mblk = row >> 7, mi = (row >> 4) & 7, g = row & 7, rb = (row >> 3) & 1;
    int kt = k >> 4, tg = (k >> 1) & 3, kb = (k >> 3) & 1;
    return (size_t)(mblk * KT + kt) * 8192 + (size_t)((((plane*8 + mi)*32 + g*4 + tg)*4 + rb + 2*kb) * 4);
}
__device__ __forceinline__ size_t boff(int n, int k, int plane, int KT){
    int nblk = n >> 7, nj = (n >> 3) & 15, g = n & 7;
    int kt = k >> 4, tg = (k >> 1) & 3, kb = (k >> 3) & 1;
    return (size_t)(nblk * KT + kt) * 8192 + (size_t)(((((nj*32 + g*4 + tg)*2 + plane)*2 + kb)) * 4);
}
__device__ __forceinline__ ull pkkey(float l, int c){
    uint32_t u = __float_as_uint(l);
    u ^= (uint32_t)((int)u >> 31) | 0x80000000u;
    return ((ull)u << 32) | (uint32_t)(2047 - c);
}
__device__ __forceinline__ void ins4u(ull* v, ull nk){
    if (nk <= v[3]) return;
    v[3] = nk;
    if (v[3] > v[2]){ ull t=v[2]; v[2]=v[3]; v[3]=t;
      if (v[2] > v[1]){ t=v[1]; v[1]=v[2]; v[2]=t;
        if (v[1] > v[0]){ t=v[0]; v[0]=v[1]; v[1]=t; } } }
}

// ============ combine W ============
__global__ void combine_w_kernel(const float* __restrict__ o_w, const float* __restrict__ v_w,
                                 const float* __restrict__ v_b, const float* __restrict__ o_b){
    int i = blockIdx.x, tx = threadIdx.x;
    __shared__ float orow[DN];
    for (int k = tx; k < DN; k += 256) orow[k] = o_w[i*DN + k];
    __syncthreads();
    float a0 = 0.f, a1 = 0.f;
    for (int k = 0; k < DN; k++){ float a = orow[k];
        a0 = fmaf(a, v_w[k*DN + tx], a0); a1 = fmaf(a, v_w[k*DN + tx + 256], a1); }
    g_Wc[i*DN + tx] = a0; g_Wc[i*DN + tx + 256] = a1;
    if (tx == 0){ float b = o_b[i];
        for (int k = 0; k < DN; k++) b = fmaf(orow[k], v_b[k], b);
        g_bc[i] = b; }
}

// ============ weight -> both-plane B image (wc, w1) ============
__global__ void wsplit_kernel(const float* __restrict__ w, uint8_t* __restrict__ img, int K, int ksh){
    int id = blockIdx.x*256 + threadIdx.x;
    int kp = id & ((K >> 1) - 1), n = id >> ksh, k = kp*2;
    uint32_t hi, lo; hsplit2(w[(size_t)n*K + k], w[(size_t)n*K + k + 1], hi, lo);
    int KT = K >> 4;
    *(uint32_t*)(img + boff(n, k, 0, KT)) = hi;
    *(uint32_t*)(img + boff(n, k, 1, KT)) = lo;
}
// ============ w2 -> hi-only dense B image ============
__global__ void wsplit_hi_kernel(const float* __restrict__ w){
    int id = blockIdx.x*256 + threadIdx.x;
    int kp = id & (HN/2 - 1), n = id >> 9, k = kp*2;
    uint32_t hi = hpack(w[(size_t)n*HN + k], w[(size_t)n*HN + k + 1]);
    int nblk = n >> 7, nj = (n >> 3) & 15, g = n & 7;
    int kt = k >> 4, tg = (k >> 1) & 3, kb = (k >> 3) & 1;
    *(uint32_t*)(g_w2h + (size_t)(nblk*64 + kt)*4096 + ((nj*32 + g*4 + tg)*2 + kb)*4) = hi;
}

// ============ x -> A fragment image ============
__global__ void xsplit_kernel(const float* __restrict__ x){
    int id = blockIdx.x*256 + threadIdx.x;
    int tg = id & 3, g = (id >> 2) & 7, mi = (id >> 5) & 7, kt = (id >> 8) & 31, mblk = id >> 13;
    uint32_t p0[4], p1[4];
#pragma unroll
    for (int rb = 0; rb < 2; rb++)
#pragma unroll
        for (int kb = 0; kb < 2; kb++){
            int row = mblk*128 + mi*16 + rb*8 + g;
            int k = kt*16 + kb*8 + tg*2;
            float2 v = *(const float2*)&x[(size_t)row*DN + k];
            hsplit2(v.x, v.y, p0[rb + 2*kb], p1[rb + 2*kb]);
        }
    size_t base = (size_t)(mblk*32 + kt)*8192 + (size_t)((mi*32 + g*4 + tg)*16);
    *(uint4*)(g_ximg + base)        = *(uint4*)p0;
    *(uint4*)(g_ximg + base + 4096) = *(uint4*)p1;
}

// ============ 3-product HMMA mainloop (attn, gemm_g) ============
__device__ __forceinline__ void issue_cp(char* smbuf, const uint8_t* A, const uint8_t* B, int tid){
    uint32_t d = smem_u32(smbuf) + (uint32_t)tid*32u;
    cpa16(d,      A + tid*32); cpa16(d + 16,        A + tid*32 + 16);
    cpa16(d+8192, B + tid*32); cpa16(d + 8192 + 16, B + tid*32 + 16);
    asm volatile("cp.async.commit_group;" ::: "memory");
}
__device__ __forceinline__ void mloop(const uint8_t* Ab, const uint8_t* Bb, int KT,
                                      char* sm, float acc[4][4][4], int tid, int wm, int wn, int lane){
    issue_cp(sm,         Ab,        Bb,        tid);
    issue_cp(sm + 16384, Ab + 8192, Bb + 8192, tid);
    for (int t = 0; t < KT; t++){
        if (t + 1 < KT) asm volatile("cp.async.wait_group 1;" ::: "memory");
        else            asm volatile("cp.async.wait_group 0;" ::: "memory");
        __syncthreads();
        if (t + 2 < KT)
            issue_cp(sm + ((t+2)%3)*16384, Ab + (size_t)(t+2)*8192, Bb + (size_t)(t+2)*8192, tid);
        char* base = sm + (t%3)*16384;
        uint32_t ah[4][4], al[4][4];
#pragma unroll
        for (int mi = 0; mi < 4; mi++){
            *(uint4*)ah[mi] = *(const uint4*)(base + (((wm*4+mi))*32 + lane)*16);
            *(uint4*)al[mi] = *(const uint4*)(base + ((8 + wm*4+mi)*32 + lane)*16);
        }
#pragma unroll
        for (int nj = 0; nj < 4; nj++){
            uint4 bv = *(const uint4*)(base + 8192 + ((wn*4+nj)*32 + lane)*16);
#pragma unroll
            for (int mi = 0; mi < 4; mi++){
                hmma(acc[mi][nj], ah[mi], bv.x, bv.y);
                hmma(acc[mi][nj], ah[mi], bv.z, bv.w);
                hmma(acc[mi][nj], al[mi], bv.x, bv.y);
            }
        }
    }
    __syncthreads();
}

// ============ attn = x @ WcT + bc ============
__global__ __launch_bounds__(256, 2)
void attn_tc(){
    __shared__ __align__(16) char sm[49152];
    int tid = threadIdx.x, wid = tid >> 5, lane = tid & 31, wm = wid & 1, wn = wid >> 1;
    int gid = lane >> 2, tig = lane & 3;
    int m0 = blockIdx.y*128, n0 = blockIdx.x*128;
    float acc[4][4][4] = {};
    mloop(g_ximg + (size_t)blockIdx.y*(DN/16)*8192, g_wcimg + (size_t)blockIdx.x*(DN/16)*8192,
          DN/16, sm, acc, tid, wm, wn, lane);
#pragma unroll
    for (int mi = 0; mi < 4; mi++)
#pragma unroll
        for (int nj = 0; nj < 4; nj++){
            int col = n0 + wn*32 + nj*8 + tig*2;
            float bx = g_bc[col], by = g_bc[col+1];
#pragma unroll
            for (int h = 0; h < 2; h++){
                int row = m0 + wm*64 + mi*16 + gid + h*8;
                float2 v = {acc[mi][nj][2*h] + bx, acc[mi][nj][2*h+1] + by};
                *(float2*)&g_attn[(size_t)row*DN + col] = v;
            }
        }
}

// ============ LN(attn+state) -> fp16 hi/lo A-image ============
__global__ __launch_bounds__(128)
void ln_split_kernel(const float* __restrict__ x, const float* __restrict__ na,
                     const float* __restrict__ lng, const float* __restrict__ lnb){
    int rr = blockIdx.x, tx = threadIdx.x, r = rr & (BRN-1);
    const float* sp = (rr < BRN) ? (na + tx*4) : (x + (size_t)r*DN + tx*4);
    float4 a = *(const float4*)&g_attn[(size_t)r*DN + tx*4];
    float4 s = *(const float4*)sp;
    float vx = a.x+s.x, vy = a.y+s.y, vz = a.z+s.z, vw = a.w+s.w;
    float sum = vx+vy+vz+vw, sq = vx*vx+vy*vy+vz*vz+vw*vw;
#pragma unroll
    for (int o = 16; o > 0; o >>= 1){
        sum += __shfl_xor_sync(0xffffffff, sum, o); sq += __shfl_xor_sync(0xffffffff, sq, o); }
    __shared__ float sh[8];
    int w = tx >> 5;
    if ((tx & 31) == 0){ sh[w] = sum; sh[4+w] = sq; }
    __syncthreads();
    float ts = sh[0]+sh[1]+sh[2]+sh[3], ts2 = sh[4]+sh[5]+sh[6]+sh[7];
    float mean = ts*(1.f/DN), rstd = rsqrtf(ts2*(1.f/DN) - mean*mean + 1e-5f);
    float4 g = *(const float4*)&lng[tx*4];
    float4 b = *(const float4*)&lnb[tx*4];
    float o0 = fmaf((vx-mean)*rstd, g.x, b.x), o1 = fmaf((vy-mean)*rstd, g.y, b.y);
    float o2 = fmaf((vz-mean)*rstd, g.z, b.z), o3 = fmaf((vw-mean)*rstd, g.w, b.w);
    uint32_t h0, l0, h1, l1; hsplit2(o0, o1, h0, l0); hsplit2(o2, o3, h1, l1);
    int k = tx*4; const int KT = DN/16;
    *(uint32_t*)(g_himg + aoff(rr, k,   0, KT)) = h0;
    *(uint32_t*)(g_himg + aoff(rr, k,   1, KT)) = l0;
    *(uint32_t*)(g_himg + aoff(rr, k+2, 0, KT)) = h1;
    *(uint32_t*)(g_himg + aoff(rr, k+2, 1, KT)) = l1;
}

// ============ g = relu(h @ w1T + b1) -> hi/lo image + exact fp32 ============
__global__ __launch_bounds__(256, 2)
void gemm_g_tc(const float* __restrict__ b1){
    __shared__ __align__(16) char sm[49152];
    int tid = threadIdx.x, wid = tid >> 5, lane = tid & 31, wm = wid & 1, wn = wid >> 1;
    int gid = lane >> 2, tig = lane & 3;
    int m0 = blockIdx.y*128, n0 = blockIdx.x*128;
    float acc[4][4][4] = {};
    mloop(g_himg + (size_t)blockIdx.y*(DN/16)*8192, g_w1img + (size_t)blockIdx.x*(DN/16)*8192,
          DN/16, sm, acc, tid, wm, wn, lane);
    const int KT = HN/16;
    float bxv[4], byv[4];
#pragma unroll
    for (int nj = 0; nj < 4; nj++){
        int col = n0 + wn*32 + nj*8 + tig*2;
        bxv[nj] = __ldg(&b1[col]); byv[nj] = __ldg(&b1[col+1]);
    }
#pragma unroll
    for (int mi = 0; mi < 4; mi++)
#pragma unroll
        for (int njp = 0; njp < 2; njp++){
            uint32_t q0[4], q1[4];
#pragma unroll
            for (int q = 0; q < 2; q++){
                int nj = njp*2 + q;
#pragma unroll
                for (int h = 0; h < 2; h++){
                    float v0 = fmaxf(acc[mi][nj][2*h]   + bxv[nj], 0.f);
                    float v1 = fmaxf(acc[mi][nj][2*h+1] + byv[nj], 0.f);
                    hsplit2(v0, v1, q0[h + 2*q], q1[h + 2*q]);
                    int row = m0 + wm*64 + mi*16 + gid + h*8;
                    int col = n0 + wn*32 + nj*8 + tig*2;
                    float2 fv = {v0, v1};
                    *(float2*)&g_f32[(size_t)row*HN + col] = fv;
                }
            }
            int kt = (n0 + wn*32 + njp*16) >> 4;
            size_t base = (size_t)(blockIdx.y*KT + kt)*8192
                        + (size_t)(((wm*4 + mi)*32 + gid*4 + tig)*16);
            *(uint4*)(g_gimg + base)        = *(uint4*)q0;
            *(uint4*)(g_gimg + base + 4096) = *(uint4*)q1;
        }
}

// ============ logits pass A: hi-only, 32-k stages, reg top-2 + approx sum ============
__global__ __launch_bounds__(256, 2)
void logits_hi2(const float* __restrict__ b2){
    extern __shared__ char dsm[];
    int tid = threadIdx.x, wid = tid >> 5, lane = tid & 31, wm = wid & 1, wn = wid >> 1;
    int gid = lane >> 2, tig = lane & 3, m0 = blockIdx.x*128;
    ull k1[8], k2[8]; float su[8];
#pragma unroll
    for (int s = 0; s < 8; s++){ k1[s] = 0; k2[s] = 0; su[s] = 0.f; }
    const uint8_t* Ab = g_gimg + (size_t)blockIdx.x*64*8192;   // hi plane = first 4KB of 8KB tile
    for (int nt = 0; nt < 16; nt++){
        const uint8_t* Bb = g_w2h + (size_t)nt*64*4096;
        float acc[4][4][4] = {};
        // prologue: chunks 0,1 (each chunk = k-16 tiles 2c,2c+1)
#pragma unroll
        for (int c = 0; c < 2; c++){
            uint32_t d = smem_u32(dsm) + c*16384u;
            cpa16(d + (tid & 255)*16,          Ab + (size_t)(2*c)*8192   + (tid & 255)*16);
            cpa16(d + 4096 + (tid & 255)*16,   Ab + (size_t)(2*c+1)*8192 + (tid & 255)*16);
            cpa16(d + 8192 + (tid & 255)*16,   Bb + (size_t)(2*c)*4096   + (tid & 255)*16);
            cpa16(d + 12288 + (tid & 255)*16,  Bb + (size_t)(2*c+1)*4096 + (tid & 255)*16);
            asm volatile("cp.async.commit_group;" ::: "memory");
        }
        for (int c = 0; c < 32; c++){
            if (c + 1 < 32) asm volatile("cp.async.wait_group 1;" ::: "memory");
            else            asm volatile("cp.async.wait_group 0;" ::: "memory");
            __syncthreads();
            if (c + 2 < 32){
                int cn = c + 2;
                uint32_t d = smem_u32(dsm) + (cn%3)*16384u;
                cpa16(d + (tid & 255)*16,         Ab + (size_t)(2*cn)*8192   + (tid & 255)*16);
                cpa16(d + 4096 + (tid & 255)*16,  Ab + (size_t)(2*cn+1)*8192 + (tid & 255)*16);
                cpa16(d + 8192 + (tid & 255)*16,  Bb + (size_t)(2*cn)*4096   + (tid & 255)*16);
                cpa16(d + 12288 + (tid & 255)*16, Bb + (size_t)(2*cn+1)*4096 + (tid & 255)*16);
                asm volatile("cp.async.commit_group;" ::: "memory");
            }
            char* st = dsm + (c%3)*16384;
#pragma unroll
            for (int sb = 0; sb < 2; sb++){
                char* Abase = st + sb*4096;
                char* Bbase = st + 8192 + sb*4096;
                uint32_t ah[4][4];
#pragma unroll
                for (int mi = 0; mi < 4; mi++)
                    *(uint4*)ah[mi] = *(const uint4*)(Abase + ((wm*4+mi)*32 + lane)*16);
#pragma unroll
                for (int nj = 0; nj < 4; nj++){
                    uint2 bv = *(const uint2*)(Bbase + ((wn*4+nj)*32 + lane)*8);
#pragma unroll
                    for (int mi = 0; mi < 4; mi++)
                        hmma(acc[mi][nj], ah[mi], bv.x, bv.y);
                }
            }
        }
        __syncthreads();   // stages dead before next nt prologue
        // fold this 128-col tile into per-thread stats (regs only)
#pragma unroll
        for (int nj = 0; nj < 4; nj++){
            int cb = nt*128 + wn*32 + nj*8 + tig*2;
            float bx = __ldg(&b2[cb]), by = __ldg(&b2[cb+1]);
#pragma unroll
            for (int mi = 0; mi < 4; mi++)
#pragma unroll
                for (int h = 0; h < 2; h++){
                    int s = mi*2 + h;
                    float l0 = acc[mi][nj][2*h] + bx, l1 = acc[mi][nj][2*h+1] + by;
                    su[s] += fexp(l0) + fexp(l1);
                    ull n0k = pkkey(l0, cb), n1k = pkkey(l1, cb + 1);
                    if (n0k > k1[s]){ k2[s] = k1[s]; k1[s] = n0k; } else if (n0k > k2[s]) k2[s] = n0k;
                    if (n1k > k1[s]){ k2[s] = k1[s]; k1[s] = n1k; } else if (n1k > k2[s]) k2[s] = n1k;
                }
        }
    }
    // merge: reuse stage smem. keys: 128 rows x 16 slots x 2 ull (32KB), ssum at +32768 (8KB)
    ull* kk = (ull*)dsm;
    float* ss = (float*)(dsm + 32768);
#pragma unroll
    for (int mi = 0; mi < 4; mi++)
#pragma unroll
        for (int h = 0; h < 2; h++){
            int row = wm*64 + mi*16 + gid + h*8, sc = wn*4 + tig, s = mi*2 + h;
            kk[(row*16 + sc)*2]     = k1[s];
            kk[(row*16 + sc)*2 + 1] = k2[s];
            ss[row*16 + sc] = su[s];
        }
    __syncthreads();
    if (tid < 128){
        int row = tid;
        float t = 0.f;
#pragma unroll
        for (int i = 0; i < 16; i++) t += ss[row*16 + i];
        g_sum[m0 + row] = t;
        ull best[4] = {0, 0, 0, 0};
        for (int i = 0; i < 32; i++) ins4u(best, kk[row*32 + i]);
#pragma unroll
        for (int j = 0; j < 4; j++)
            g_ci4[(m0 + row)*4 + j] = 2047 - (int)(uint32_t)(best[j] & 0xFFFFFFFFull);
    }
}

// ============ rescue: exact fp32 rescore of 4 candidates, warp per row ============
__global__ __launch_bounds__(256)
void rescue_kernel(const float* __restrict__ w2, const float* __restrict__ b2){
    int row = blockIdx.x*8 + (threadIdx.x >> 5);
    int lane = threadIdx.x & 31;
    float bestv = -1e30f; int besti = 1 << 30;
    const float* gr = g_f32 + (size_t)row * HN;
#pragma unroll 1
    for (int j = 0; j < 4; j++){
        int c = g_ci4[row*4 + j];
        const float* wr = w2 + (size_t)c * HN;
        float p = 0.f;
        for (int k = lane; k < HN; k += 32) p = fmaf(gr[k], wr[k], p);
#pragma unroll
        for (int o = 16; o > 0; o >>= 1) p += __shfl_xor_sync(0xffffffff, p, o);
        p += __ldg(&b2[c]);
        if (p > bestv || (p == bestv && c < besti)){ bestv = p; besti = c; }
    }
    if (lane == 0){ g_lmax[row] = bestv; g_arg[row] = besti; }
}

// ============ finalize ============
__global__ void finalize_kernel(float* __restrict__ out){
    int r = blockIdx.x*256 + threadIdx.x;
    if (r >= BRN) return;
    float m0 = __expf(g_lmax[r]) / g_sum[r];
    float m1 = __expf(g_lmax[BRN + r]) / g_sum[BRN + r];
    int i0 = g_arg[r], i1 = g_arg[BRN + r];
    bool c0 = (i0 != 0) && (m0 >= 0.1f);
    bool c1 = c0 && (i1 != 0) && (m1 >= 0.1f);
    out[r] = c0 ? (c1 ? m0*m1 : m0) : 0.f;
    out[BRN + r] = (float)i0; out[2*BRN + r] = (float)i1;
    out[3*BRN + r] = (float)((int)c0 + (int)c1);
}

extern "C" void kernel_launch(void* const* d_in, const int* in_sizes, int n_in,
                              void* d_out, int out_size){
    const float* x    = (const float*)d_in[0];
    const float* na   = (const float*)d_in[1];
    const float* v_w  = (const float*)d_in[2];
    const float* v_b  = (const float*)d_in[3];
    const float* o_w  = (const float*)d_in[4];
    const float* o_b  = (const float*)d_in[5];
    const float* ln_g = (const float*)d_in[6];
    const float* ln_b = (const float*)d_in[7];
    const float* w1   = (const float*)d_in[8];
    const float* b1   = (const float*)d_in[9];
    const float* w2   = (const float*)d_in[10];
    const float* b2   = (const float*)d_in[11];
    float* out = (float*)d_out;

    float* wc; cudaGetSymbolAddress((void**)&wc, g_Wc);
    uint8_t *wcimg, *w1img;
    cudaGetSymbolAddress((void**)&wcimg, g_wcimg);
    cudaGetSymbolAddress((void**)&w1img, g_w1img);
    cudaFuncSetAttribute(logits_hi2, cudaFuncAttributeMaxDynamicSharedMemorySize, 49152);

    combine_w_kernel<<<DN, 256>>>(o_w, v_w, v_b, o_b);
    wsplit_kernel<<<(DN*DN/2)/256, 256>>>(wc, wcimg, DN, 8);
    wsplit_kernel<<<(HN*DN/2)/256, 256>>>(w1, w1img, DN, 8);
    wsplit_hi_kernel<<<((size_t)NRELN*HN/2)/256, 256>>>(w2);
    xsplit_kernel<<<(BRN*DN/8)/256, 256>>>(x);
    attn_tc<<<dim3(DN/128, BRN/128), 256>>>();
    ln_split_kernel<<<ROWS2, 128>>>(x, na, ln_g, ln_b);
    gemm_g_tc<<<dim3(HN/128, ROWS2/128), 256>>>(b1);
    logits_hi2<<<ROWS2/128, 256, 49152>>>(b2);
    rescue_kernel<<<ROWS2/8, 256>>>(w2, b2);
    finalize_kernel<<<BRN/256, 256>>>(out);
}

// round 12
// speedup vs baseline: 1.8346x; 1.0214x over previous
#include <cuda_runtime.h>
#include <cuda_fp16.h>
#include <cstdint>

#define BRN 32768
#define DN 512
#define HN 1024
#define NRELN 2048
#define ROWS2 65536
typedef unsigned long long ull;

__device__ float g_attn[(size_t)BRN * DN];
__device__ float g_Wc[DN * DN];
__device__ float g_bc[DN];
__device__ uint8_t g_ximg[(size_t)(BRN/128)*(DN/16)*8192];
__device__ uint8_t g_wcimg[(size_t)(DN/128)*(DN/16)*8192];
__device__ uint8_t g_himg[(size_t)(ROWS2/128)*(DN/16)*8192];
__device__ uint8_t g_w1img[(size_t)(HN/128)*(DN/16)*8192];
__device__ uint8_t g_gh2[(size_t)(ROWS2/128)*(HN/16)*4096];   // hi-only dense g image
__device__ uint8_t g_w2h[(size_t)(NRELN/128)*(HN/16)*4096];
__device__ float   g_f32[(size_t)ROWS2 * HN];
__device__ float g_sumh[2][ROWS2];
__device__ ull   g_keys[2][ROWS2][4];
__device__ float g_sum[ROWS2];
__device__ int   g_ci4[ROWS2 * 4];
__device__ float g_lmax[ROWS2];
__device__ int   g_arg[ROWS2];

__device__ __forceinline__ uint32_t smem_u32(const void* p){
    uint32_t a; asm("{ .reg .u64 t; cvta.to.shared.u64 t, %1; cvt.u32.u64 %0, t; }" : "=r"(a) : "l"(p)); return a;
}
__device__ __forceinline__ void cpa16(uint32_t d, const void* s){
    asm volatile("cp.async.cg.shared.global [%0],[%1],16;" :: "r"(d), "l"(s));
}
__device__ __forceinline__ void hmma(float* c, const uint32_t* a, uint32_t b0, uint32_t b1){
    asm volatile("mma.sync.aligned.m16n8k16.row.col.f32.f16.f16.f32 {%0,%1,%2,%3},{%4,%5,%6,%7},{%8,%9},{%0,%1,%2,%3};"
        : "+f"(c[0]), "+f"(c[1]), "+f"(c[2]), "+f"(c[3])
        : "r"(a[0]), "r"(a[1]), "r"(a[2]), "r"(a[3]), "r"(b0), "r"(b1));
}
__device__ __forceinline__ float fexp(float x){
    x = fmaxf(x, -80.f);
    return __uint_as_float((uint32_t)(int)(fmaf(x, 12102203.0f, 1064866805.0f)));
}
__device__ __forceinline__ uint32_t hpack(float x, float y){
    return (uint32_t)__half_as_ushort(__float2half_rn(x)) | ((uint32_t)__half_as_ushort(__float2half_rn(y)) << 16);
}
__device__ __forceinline__ void hsplit2(float x, float y, uint32_t& hi, uint32_t& lo){
    __half hx = __float2half_rn(x), hy = __float2half_rn(y);
    __half lx = __float2half_rn(x - __half2float(hx)), ly = __float2half_rn(y - __half2float(hy));
    hi = (uint32_t)__half_as_ushort(hx) | ((uint32_t)__half_as_ushort(hy) << 16);
    lo = (uint32_t)__half_as_ushort(lx) | ((uint32_t)__half_as_ushort(ly) << 16);
}
__device__ __forceinline__ size_t aoff(int row, int k, int plane, int KT){
    int mblk = row >> 7, mi = (row >> 4) & 7, g = row & 7, rb = (row >> 3) & 1;
    int kt = k >> 4, tg = (k >> 1) & 3, kb = (k >> 3) & 1;
    return (size_t)(mblk * KT + kt) * 8192 + (size_t)((((plane*8 + mi)*32 + g*4 + tg)*4 + rb + 2*kb) * 4);
}
__device__ __forceinline__ size_t boff(int n, int k, int plane, int KT){
    int nblk = n >> 7, nj = (n >> 3) & 15, g = n & 7;
    int kt = k >> 4, tg = (k >> 1) & 3, kb = (k >> 3) & 1;
    return (size_t)(nblk * KT + kt) * 8192 + (size_t)(((((nj*32 + g*4 + tg)*2 + plane)*2 + kb)) * 4);
}
__device__ __forceinline__ ull pkkey(float l, int c){
    uint32_t u = __float_as_uint(l);
    u ^= (uint32_t)((int)u >> 31) | 0x80000000u;
    return ((ull)u << 32) | (uint32_t)(2047 - c);
}
__device__ __forceinline__ void ins4u(ull* v, ull nk){
    if (nk <= v[3]) return;
    v[3] = nk;
    if (v[3] > v[2]){ ull t=v[2]; v[2]=v[3]; v[3]=t;
      if (v[2] > v[1]){ t=v[1]; v[1]=v[2]; v[2]=t;
        if (v[1] > v[0]){ t=v[0]; v[0]=v[1]; v[1]=t; } } }
}

// ============ combine W ============
__global__ void combine_w_kernel(const float* __restrict__ o_w, const float* __restrict__ v_w,
                                 const float* __restrict__ v_b, const float* __restrict__ o_b){
    int i = blockIdx.x, tx = threadIdx.x;
    __shared__ float orow[DN];
    for (int k = tx; k < DN; k += 256) orow[k] = o_w[i*DN + k];
    __syncthreads();
    float a0 = 0.f, a1 = 0.f;
    for (int k = 0; k < DN; k++){ float a = orow[k];
        a0 = fmaf(a, v_w[k*DN + tx], a0); a1 = fmaf(a, v_w[k*DN + tx + 256], a1); }
    g_Wc[i*DN + tx] = a0; g_Wc[i*DN + tx + 256] = a1;
    if (tx == 0){ float b = o_b[i];
        for (int k = 0; k < DN; k++) b = fmaf(orow[k], v_b[k], b);
        g_bc[i] = b; }
}

// ============ weight -> both-plane B image (wc, w1) ============
__global__ void wsplit_kernel(const float* __restrict__ w, uint8_t* __restrict__ img, int K, int ksh){
    int id = blockIdx.x*256 + threadIdx.x;
    int kp = id & ((K >> 1) - 1), n = id >> ksh, k = kp*2;
    uint32_t hi, lo; hsplit2(w[(size_t)n*K + k], w[(size_t)n*K + k + 1], hi, lo);
    int KT = K >> 4;
    *(uint32_t*)(img + boff(n, k, 0, KT)) = hi;
    *(uint32_t*)(img + boff(n, k, 1, KT)) = lo;
}
// ============ w2 -> hi-only dense B image ============
__global__ void wsplit_hi_kernel(const float* __restrict__ w){
    int id = blockIdx.x*256 + threadIdx.x;
    int kp = id & (HN/2 - 1), n = id >> 9, k = kp*2;
    uint32_t hi = hpack(w[(size_t)n*HN + k], w[(size_t)n*HN + k + 1]);
    int nblk = n >> 7, nj = (n >> 3) & 15, g = n & 7;
    int kt = k >> 4, tg = (k >> 1) & 3, kb = (k >> 3) & 1;
    *(uint32_t*)(g_w2h + (size_t)(nblk*64 + kt)*4096 + ((nj*32 + g*4 + tg)*2 + kb)*4) = hi;
}

// ============ x -> A fragment image ============
__global__ void xsplit_kernel(const float* __restrict__ x){
    int id = blockIdx.x*256 + threadIdx.x;
    int tg = id & 3, g = (id >> 2) & 7, mi = (id >> 5) & 7, kt = (id >> 8) & 31, mblk = id >> 13;
    uint32_t p0[4], p1[4];
#pragma unroll
    for (int rb = 0; rb < 2; rb++)
#pragma unroll
        for (int kb = 0; kb < 2; kb++){
            int row = mblk*128 + mi*16 + rb*8 + g;
            int k = kt*16 + kb*8 + tg*2;
            float2 v = *(const float2*)&x[(size_t)row*DN + k];
            hsplit2(v.x, v.y, p0[rb + 2*kb], p1[rb + 2*kb]);
        }
    size_t base = (size_t)(mblk*32 + kt)*8192 + (size_t)((mi*32 + g*4 + tg)*16);
    *(uint4*)(g_ximg + base)        = *(uint4*)p0;
    *(uint4*)(g_ximg + base + 4096) = *(uint4*)p1;
}

// ============ 3-product HMMA mainloop (attn, gemm_g) ============
__device__ __forceinline__ void issue_cp(char* smbuf, const uint8_t* A, const uint8_t* B, int tid){
    uint32_t d = smem_u32(smbuf) + (uint32_t)tid*32u;
    cpa16(d,      A + tid*32); cpa16(d + 16,        A + tid*32 + 16);
    cpa16(d+8192, B + tid*32); cpa16(d + 8192 + 16, B + tid*32 + 16);
    asm volatile("cp.async.commit_group;" ::: "memory");
}
__device__ __forceinline__ void mloop(const uint8_t* Ab, const uint8_t* Bb, int KT,
                                      char* sm, float acc[4][4][4], int tid, int wm, int wn, int lane){
    issue_cp(sm,         Ab,        Bb,        tid);
    issue_cp(sm + 16384, Ab + 8192, Bb + 8192, tid);
    for (int t = 0; t < KT; t++){
        if (t + 1 < KT) asm volatile("cp.async.wait_group 1;" ::: "memory");
        else            asm volatile("cp.async.wait_group 0;" ::: "memory");
        __syncthreads();
        if (t + 2 < KT)
            issue_cp(sm + ((t+2)%3)*16384, Ab + (size_t)(t+2)*8192, Bb + (size_t)(t+2)*8192, tid);
        char* base = sm + (t%3)*16384;
        uint32_t ah[4][4], al[4][4];
#pragma unroll
        for (int mi = 0; mi < 4; mi++){
            *(uint4*)ah[mi] = *(const uint4*)(base + (((wm*4+mi))*32 + lane)*16);
            *(uint4*)al[mi] = *(const uint4*)(base + ((8 + wm*4+mi)*32 + lane)*16);
        }
#pragma unroll
        for (int nj = 0; nj < 4; nj++){
            uint4 bv = *(const uint4*)(base + 8192 + ((wn*4+nj)*32 + lane)*16);
#pragma unroll
            for (int mi = 0; mi < 4; mi++){
                hmma(acc[mi][nj], ah[mi], bv.x, bv.y);
                hmma(acc[mi][nj], ah[mi], bv.z, bv.w);
                hmma(acc[mi][nj], al[mi], bv.x, bv.y);
            }
        }
    }
    __syncthreads();
}

// ============ attn = x @ WcT + bc ============
__global__ __launch_bounds__(256, 2)
void attn_tc(){
    __shared__ __align__(16) char sm[49152];
    int tid = threadIdx.x, wid = tid >> 5, lane = tid & 31, wm = wid & 1, wn = wid >> 1;
    int gid = lane >> 2, tig = lane & 3;
    int m0 = blockIdx.y*128, n0 = blockIdx.x*128;
    float acc[4][4][4] = {};
    mloop(g_ximg + (size_t)blockIdx.y*(DN/16)*8192, g_wcimg + (size_t)blockIdx.x*(DN/16)*8192,
          DN/16, sm, acc, tid, wm, wn, lane);
#pragma unroll
    for (int mi = 0; mi < 4; mi++)
#pragma unroll
        for (int nj = 0; nj < 4; nj++){
            int col = n0 + wn*32 + nj*8 + tig*2;
            float bx = g_bc[col], by = g_bc[col+1];
#pragma unroll
            for (int h = 0; h < 2; h++){
                int row = m0 + wm*64 + mi*16 + gid + h*8;
                float2 v = {acc[mi][nj][2*h] + bx, acc[mi][nj][2*h+1] + by};
                *(float2*)&g_attn[(size_t)row*DN + col] = v;
            }
        }
}

// ============ LN(attn+state) -> fp16 hi/lo A-image ============
__global__ __launch_bounds__(128)
void ln_split_kernel(const float* __restrict__ x, const float* __restrict__ na,
                     const float* __restrict__ lng, const float* __restrict__ lnb){
    int rr = blockIdx.x, tx = threadIdx.x, r = rr & (BRN-1);
    const float* sp = (rr < BRN) ? (na + tx*4) : (x + (size_t)r*DN + tx*4);
    float4 a = *(const float4*)&g_attn[(size_t)r*DN + tx*4];
    float4 s = *(const float4*)sp;
    float vx = a.x+s.x, vy = a.y+s.y, vz = a.z+s.z, vw = a.w+s.w;
    float sum = vx+vy+vz+vw, sq = vx*vx+vy*vy+vz*vz+vw*vw;
#pragma unroll
    for (int o = 16; o > 0; o >>= 1){
        sum += __shfl_xor_sync(0xffffffff, sum, o); sq += __shfl_xor_sync(0xffffffff, sq, o); }
    __shared__ float sh[8];
    int w = tx >> 5;
    if ((tx & 31) == 0){ sh[w] = sum; sh[4+w] = sq; }
    __syncthreads();
    float ts = sh[0]+sh[1]+sh[2]+sh[3], ts2 = sh[4]+sh[5]+sh[6]+sh[7];
    float mean = ts*(1.f/DN), rstd = rsqrtf(ts2*(1.f/DN) - mean*mean + 1e-5f);
    float4 g = *(const float4*)&lng[tx*4];
    float4 b = *(const float4*)&lnb[tx*4];
    float o0 = fmaf((vx-mean)*rstd, g.x, b.x), o1 = fmaf((vy-mean)*rstd, g.y, b.y);
    float o2 = fmaf((vz-mean)*rstd, g.z, b.z), o3 = fmaf((vw-mean)*rstd, g.w, b.w);
    uint32_t h0, l0, h1, l1; hsplit2(o0, o1, h0, l0); hsplit2(o2, o3, h1, l1);
    int k = tx*4; const int KT = DN/16;
    *(uint32_t*)(g_himg + aoff(rr, k,   0, KT)) = h0;
    *(uint32_t*)(g_himg + aoff(rr, k,   1, KT)) = l0;
    *(uint32_t*)(g_himg + aoff(rr, k+2, 0, KT)) = h1;
    *(uint32_t*)(g_himg + aoff(rr, k+2, 1, KT)) = l1;
}

// ============ g = relu(h @ w1T + b1) -> hi-dense image + exact fp32 ============
__global__ __launch_bounds__(256, 2)
void gemm_g_tc(const float* __restrict__ b1){
    __shared__ __align__(16) char sm[49152];
    int tid = threadIdx.x, wid = tid >> 5, lane = tid & 31, wm = wid & 1, wn = wid >> 1;
    int gid = lane >> 2, tig = lane & 3;
    int m0 = blockIdx.y*128, n0 = blockIdx.x*128;
    float acc[4][4][4] = {};
    mloop(g_himg + (size_t)blockIdx.y*(DN/16)*8192, g_w1img + (size_t)blockIdx.x*(DN/16)*8192,
          DN/16, sm, acc, tid, wm, wn, lane);
    const int KT = HN/16;
    float bxv[4], byv[4];
#pragma unroll
    for (int nj = 0; nj < 4; nj++){
        int col = n0 + wn*32 + nj*8 + tig*2;
        bxv[nj] = __ldg(&b1[col]); byv[nj] = __ldg(&b1[col+1]);
    }
#pragma unroll
    for (int mi = 0; mi < 4; mi++)
#pragma unroll
        for (int njp = 0; njp < 2; njp++){
            uint32_t q0[4];
#pragma unroll
            for (int q = 0; q < 2; q++){
                int nj = njp*2 + q;
#pragma unroll
                for (int h = 0; h < 2; h++){
                    float v0 = fmaxf(acc[mi][nj][2*h]   + bxv[nj], 0.f);
                    float v1 = fmaxf(acc[mi][nj][2*h+1] + byv[nj], 0.f);
                    q0[h + 2*q] = hpack(v0, v1);
                    int row = m0 + wm*64 + mi*16 + gid + h*8;
                    int col = n0 + wn*32 + nj*8 + tig*2;
                    float2 fv = {v0, v1};
                    *(float2*)&g_f32[(size_t)row*HN + col] = fv;
                }
            }
            int kt = (n0 + wn*32 + njp*16) >> 4;
            size_t base = (size_t)(blockIdx.y*KT + kt)*4096
                        + (size_t)(((wm*4 + mi)*32 + gid*4 + tig)*16);
            *(uint4*)(g_gh2 + base) = *(uint4*)q0;
        }
}

// ============ logits pass A: hi-only, split in 2 column halves ============
__global__ __launch_bounds__(256, 2)
void logits_hi2(const float* __restrict__ b2){
    extern __shared__ char dsm[];
    int tid = threadIdx.x, wid = tid >> 5, lane = tid & 31, wm = wid & 1, wn = wid >> 1;
    int gid = lane >> 2, tig = lane & 3;
    int m0 = blockIdx.y*128, half = blockIdx.x;
    ull k1[8], k2[8]; float su[8];
#pragma unroll
    for (int s = 0; s < 8; s++){ k1[s] = 0; k2[s] = 0; su[s] = 0.f; }
    const uint8_t* Ab = g_gh2 + (size_t)blockIdx.y*64*4096;   // 64 dense 4KB tiles
    for (int nt = half*8; nt < half*8 + 8; nt++){
        const uint8_t* Bb = g_w2h + (size_t)nt*64*4096;
        float acc[4][4][4] = {};
        // chunk c = k-tiles 2c,2c+1 : A 8KB contiguous, B 8KB contiguous
        issue_cp(dsm,         Ab,        Bb,        tid);
        issue_cp(dsm + 16384, Ab + 8192, Bb + 8192, tid);
        for (int c = 0; c < 32; c++){
            if (c + 1 < 32) asm volatile("cp.async.wait_group 1;" ::: "memory");
            else            asm volatile("cp.async.wait_group 0;" ::: "memory");
            __syncthreads();
            if (c + 2 < 32)
                issue_cp(dsm + ((c+2)%3)*16384, Ab + (size_t)(c+2)*8192, Bb + (size_t)(c+2)*8192, tid);
            char* st = dsm + (c%3)*16384;
#pragma unroll
            for (int sb = 0; sb < 2; sb++){
                char* Abase = st + sb*4096;
                char* Bbase = st + 8192 + sb*4096;
                uint32_t ah[4][4];
#pragma unroll
                for (int mi = 0; mi < 4; mi++)
                    *(uint4*)ah[mi] = *(const uint4*)(Abase + ((wm*4+mi)*32 + lane)*16);
#pragma unroll
                for (int nj = 0; nj < 4; nj++){
                    uint2 bv = *(const uint2*)(Bbase + ((wn*4+nj)*32 + lane)*8);
#pragma unroll
                    for (int mi = 0; mi < 4; mi++)
                        hmma(acc[mi][nj], ah[mi], bv.x, bv.y);
                }
            }
        }
        __syncthreads();
#pragma unroll
        for (int nj = 0; nj < 4; nj++){
            int cb = nt*128 + wn*32 + nj*8 + tig*2;
            float bx = __ldg(&b2[cb]), by = __ldg(&b2[cb+1]);
#pragma unroll
            for (int mi = 0; mi < 4; mi++)
#pragma unroll
                for (int h = 0; h < 2; h++){
                    int s = mi*2 + h;
                    float l0 = acc[mi][nj][2*h] + bx, l1 = acc[mi][nj][2*h+1] + by;
                    su[s] += fexp(l0) + fexp(l1);
                    ull n0k = pkkey(l0, cb), n1k = pkkey(l1, cb + 1);
                    if (n0k > k1[s]){ k2[s] = k1[s]; k1[s] = n0k; } else if (n0k > k2[s]) k2[s] = n0k;
                    if (n1k > k1[s]){ k2[s] = k1[s]; k1[s] = n1k; } else if (n1k > k2[s]) k2[s] = n1k;
                }
        }
    }
    ull* kk = (ull*)dsm;
    float* ss = (float*)(dsm + 32768);
#pragma unroll
    for (int mi = 0; mi < 4; mi++)
#pragma unroll
        for (int h = 0; h < 2; h++){
            int row = wm*64 + mi*16 + gid + h*8, sc = wn*4 + tig, s = mi*2 + h;
            kk[(row*16 + sc)*2]     = k1[s];
            kk[(row*16 + sc)*2 + 1] = k2[s];
            ss[row*16 + sc] = su[s];
        }
    __syncthreads();
    if (tid < 128){
        int row = tid;
        float t = 0.f;
#pragma unroll
        for (int i = 0; i < 16; i++) t += ss[row*16 + i];
        g_sumh[half][m0 + row] = t;
        ull best[4] = {0, 0, 0, 0};
        for (int i = 0; i < 32; i++) ins4u(best, kk[row*32 + i]);
#pragma unroll
        for (int j = 0; j < 4; j++) g_keys[half][m0 + row][j] = best[j];
    }
}

// ============ merge halves ============
__global__ void merge_kernel(){
    int r = blockIdx.x*256 + threadIdx.x;
    ull best[4] = {0, 0, 0, 0};
#pragma unroll
    for (int hf = 0; hf < 2; hf++)
#pragma unroll
        for (int j = 0; j < 4; j++) ins4u(best, g_keys[hf][r][j]);
#pragma unroll
    for (int j = 0; j < 4; j++)
        g_ci4[r*4 + j] = 2047 - (int)(uint32_t)(best[j] & 0xFFFFFFFFull);
    g_sum[r] = g_sumh[0][r] + g_sumh[1][r];
}

// ============ rescue: exact fp32 rescore of 4 candidates, warp per row ============
__global__ __launch_bounds__(256)
void rescue_kernel(const float* __restrict__ w2, const float* __restrict__ b2){
    int row = blockIdx.x*8 + (threadIdx.x >> 5);
    int lane = threadIdx.x & 31;
    float bestv = -1e30f; int besti = 1 << 30;
    const float* gr = g_f32 + (size_t)row * HN;
#pragma unroll 1
    for (int j = 0; j < 4; j++){
        int c = g_ci4[row*4 + j];
        const float* wr = w2 + (size_t)c * HN;
        float p = 0.f;
        for (int k = lane; k < HN; k += 32) p = fmaf(gr[k], wr[k], p);
#pragma unroll
        for (int o = 16; o > 0; o >>= 1) p += __shfl_xor_sync(0xffffffff, p, o);
        p += __ldg(&b2[c]);
        if (p > bestv || (p == bestv && c < besti)){ bestv = p; besti = c; }
    }
    if (lane == 0){ g_lmax[row] = bestv; g_arg[row] = besti; }
}

// ============ finalize ============
__global__ void finalize_kernel(float* __restrict__ out){
    int r = blockIdx.x*256 + threadIdx.x;
    if (r >= BRN) return;
    float m0 = __expf(g_lmax[r]) / g_sum[r];
    float m1 = __expf(g_lmax[BRN + r]) / g_sum[BRN + r];
    int i0 = g_arg[r], i1 = g_arg[BRN + r];
    bool c0 = (i0 != 0) && (m0 >= 0.1f);
    bool c1 = c0 && (i1 != 0) && (m1 >= 0.1f);
    out[r] = c0 ? (c1 ? m0*m1 : m0) : 0.f;
    out[BRN + r] = (float)i0; out[2*BRN + r] = (float)i1;
    out[3*BRN + r] = (float)((int)c0 + (int)c1);
}

extern "C" void kernel_launch(void* const* d_in, const int* in_sizes, int n_in,
                              void* d_out, int out_size){
    const float* x    = (const float*)d_in[0];
    const float* na   = (const float*)d_in[1];
    const float* v_w  = (const float*)d_in[2];
    const float* v_b  = (const float*)d_in[3];
    const float* o_w  = (const float*)d_in[4];
    const float* o_b  = (const float*)d_in[5];
    const float* ln_g = (const float*)d_in[6];
    const float* ln_b = (const float*)d_in[7];
    const float* w1   = (const float*)d_in[8];
    const float* b1   = (const float*)d_in[9];
    const float* w2   = (const float*)d_in[10];
    const float* b2   = (const float*)d_in[11];
    float* out = (float*)d_out;

    float* wc; cudaGetSymbolAddress((void**)&wc, g_Wc);
    uint8_t *wcimg, *w1img;
    cudaGetSymbolAddress((void**)&wcimg, g_wcimg);
    cudaGetSymbolAddress((void**)&w1img, g_w1img);
    cudaFuncSetAttribute(logits_hi2, cudaFuncAttributeMaxDynamicSharedMemorySize, 49152);

    combine_w_kernel<<<DN, 256>>>(o_w, v_w, v_b, o_b);
    wsplit_kernel<<<(DN*DN/2)/256, 256>>>(wc, wcimg, DN, 8);
    wsplit_kernel<<<(HN*DN/2)/256, 256>>>(w1, w1img, DN, 8);
    wsplit_hi_kernel<<<((size_t)NRELN*HN/2)/256, 256>>>(w2);
    xsplit_kernel<<<(BRN*DN/8)/256, 256>>>(x);
    attn_tc<<<dim3(DN/128, BRN/128), 256>>>();
    ln_split_kernel<<<ROWS2, 128>>>(x, na, ln_g, ln_b);
    gemm_g_tc<<<dim3(HN/128, ROWS2/128), 256>>>(b1);
    logits_hi2<<<dim3(2, ROWS2/128), 256, 49152>>>(b2);
    merge_kernel<<<ROWS2/256, 256>>>();
    rescue_kernel<<<ROWS2/8, 256>>>(w2, b2);
    finalize_kernel<<<BRN/256, 256>>>(out);
}